// round 14
// baseline (speedup 1.0000x reference)
#include <cuda_runtime.h>
#include <cuda_bf16.h>
#include <math.h>
#include <stdint.h>

#define NB  2
#define SEQ 2048
#define DM  1024
#define NH  16
#define DH  64
#define MTOT (NB*SEQ)   // 4096
#define NCH (SEQ/128)   // 16

// ---------------- scratch (device globals; no allocation allowed) -------------
__device__ __nv_bfloat16 g_xh [(size_t)MTOT*DM],  g_xl [(size_t)MTOT*DM];
__device__ __nv_bfloat16 g_wqh[(size_t)3*DM*DM],  g_wql[(size_t)3*DM*DM];
__device__ __nv_bfloat16 g_woh[(size_t)DM*DM],    g_wol[(size_t)DM*DM];
__device__ __nv_bfloat16 g_qh [(size_t)NB*NH*SEQ*DH], g_ql[(size_t)NB*NH*SEQ*DH];
__device__ __nv_bfloat16 g_kh [(size_t)NB*NH*SEQ*DH], g_kl[(size_t)NB*NH*SEQ*DH];
__device__ __nv_bfloat16 g_vth[(size_t)NB*NH*DH*SEQ], g_vtl[(size_t)NB*NH*DH*SEQ];
__device__ __nv_bfloat16 g_ctxh[(size_t)MTOT*DM], g_ctxl[(size_t)MTOT*DM];
__device__ float g_pv[(size_t)NB*NH*SEQ];

// ======================= helpers ==============================================
__device__ __forceinline__ unsigned smem_u32(const void* p) {
    unsigned a;
    asm("{ .reg .u64 t; cvta.to.shared.u64 t, %1; cvt.u32.u64 %0, t; }" : "=r"(a) : "l"(p));
    return a;
}
__device__ __forceinline__ void ldsm4(unsigned addr, uint32_t r[4]) {
    asm volatile("ldmatrix.sync.aligned.m8n8.x4.shared.b16 {%0,%1,%2,%3}, [%4];"
        : "=r"(r[0]), "=r"(r[1]), "=r"(r[2]), "=r"(r[3]) : "r"(addr));
}
__device__ __forceinline__ void mmabf(float d[4], const uint32_t a[4], const uint32_t b[2]) {
    asm volatile("mma.sync.aligned.m16n8k16.row.col.f32.bf16.bf16.f32 "
        "{%0,%1,%2,%3},{%4,%5,%6,%7},{%8,%9},{%0,%1,%2,%3};"
        : "+f"(d[0]), "+f"(d[1]), "+f"(d[2]), "+f"(d[3])
        : "r"(a[0]), "r"(a[1]), "r"(a[2]), "r"(a[3]), "r"(b[0]), "r"(b[1]));
}
__device__ __forceinline__ void split_hl(float v, __nv_bfloat16& h, __nv_bfloat16& l) {
    h = __float2bfloat16(v);
    l = __float2bfloat16(v - __bfloat162float(h));
}
__device__ __forceinline__ uint32_t pack_hl_hi(float a, float b) {
    __nv_bfloat162 hv; hv.x = __float2bfloat16(a); hv.y = __float2bfloat16(b);
    return *(uint32_t*)&hv;
}
__device__ __forceinline__ uint32_t pack_hl_lo(float a, float b) {
    __nv_bfloat16 ha = __float2bfloat16(a), hb = __float2bfloat16(b);
    __nv_bfloat162 lv;
    lv.x = __float2bfloat16(a - __bfloat162float(ha));
    lv.y = __float2bfloat16(b - __bfloat162float(hb));
    return *(uint32_t*)&lv;
}
__device__ __forceinline__ void cp16(unsigned saddr, const void* gaddr) {
    asm volatile("cp.async.cg.shared.global [%0], [%1], 16;" :: "r"(saddr), "l"(gaddr));
}
#define CP_COMMIT() asm volatile("cp.async.commit_group;" ::: "memory")
#define CP_WAIT(n)  asm volatile("cp.async.wait_group %0;" :: "n"(n) : "memory")

// ---------------- fp32 -> bf16 hi/lo conversion -------------------------------
__global__ void __launch_bounds__(256) cvt_kernel(const float* __restrict__ in,
                                                  __nv_bfloat16* __restrict__ oh,
                                                  __nv_bfloat16* __restrict__ ol, int n)
{
    for (int i = blockIdx.x*256 + threadIdx.x; i < n; i += gridDim.x*256) {
        __nv_bfloat16 h, l;
        split_hl(in[i], h, l);
        oh[i] = h; ol[i] = l;
    }
}

// ---------------- generic bf16x3 GEMM: C = A @ B^T + bias ---------------------
// 256 threads, tile 128(M) x 64(N), BK=32, 3-stage cp.async, 2 CTAs/SM.
#define GS_AH 0u
#define GS_AL 10240u
#define GS_BH 20480u
#define GS_BL 25600u
#define GS_STAGE 30720u
#define GEMM_SMEM (3u*GS_STAGE)

template <int MODE>
__global__ void __launch_bounds__(256, 2) gemm_kernel(const __nv_bfloat16* __restrict__ Ah,
                                                      const __nv_bfloat16* __restrict__ Al,
                                                      const __nv_bfloat16* __restrict__ Bh,
                                                      const __nv_bfloat16* __restrict__ Bl,
                                                      const float* __restrict__ bias,
                                                      float* __restrict__ Cout)
{
    extern __shared__ char smc[];
    const unsigned sb = smem_u32(smc);
    const int t = threadIdx.x, lane = t & 31, w = t >> 5;
    const int warpm = w >> 1, warpn = w & 1;
    const int blockM = blockIdx.y * 128, blockN = blockIdx.x * 64;
    const int gq = lane >> 2, tg = lane & 3;

    const int prow = t >> 2;                     // 0..63
    const int pcol = (t & 3) << 3;               // bf16 col (8 per 16B)
    const unsigned pso = (unsigned)(prow*80 + (t & 3)*16);

    float acc[2][4][4] = {};

    auto prefetch = [&](int kt, int s) {
        unsigned st = sb + (unsigned)s*GS_STAGE;
        int k0 = kt*32;
        #pragma unroll
        for (int p = 0; p < 2; p++) {
            int row = prow + p*64;
            size_t ga = (size_t)(blockM + row)*DM + k0 + pcol;
            cp16(st + GS_AH + pso + (unsigned)p*64*80, Ah + ga);
            cp16(st + GS_AL + pso + (unsigned)p*64*80, Al + ga);
        }
        size_t gb = (size_t)(blockN + prow)*DM + k0 + pcol;
        cp16(st + GS_BH + pso, Bh + gb);
        cp16(st + GS_BL + pso, Bl + gb);
    };

    prefetch(0, 0); CP_COMMIT();
    prefetch(1, 1); CP_COMMIT();

    for (int kt = 0; kt < 32; kt++) {
        if (kt + 2 < 32) { prefetch(kt+2, (kt+2)%3); CP_COMMIT(); CP_WAIT(2); }
        else CP_WAIT(0);
        __syncthreads();
        const unsigned st = sb + (unsigned)(kt % 3)*GS_STAGE;

        // B fragments for the whole k-tile (k=32 = both ksteps)
        uint32_t bhv[4][4], blv[4][4];
        #pragma unroll
        for (int nt = 0; nt < 4; nt++) {
            unsigned brow = (unsigned)(warpn*32 + nt*8 + (lane & 7));
            unsigned boff = brow*80 + (lane >> 3)*16;
            ldsm4(st + GS_BH + boff, bhv[nt]);
            ldsm4(st + GS_BL + boff, blv[nt]);
        }
        #pragma unroll
        for (int ks = 0; ks < 2; ks++) {
            uint32_t ah[2][4], al[2][4];
            #pragma unroll
            for (int mt = 0; mt < 2; mt++) {
                unsigned arow = (unsigned)(warpm*32 + mt*16 + (lane & 15));
                unsigned aoff = arow*80 + ks*32 + (lane >> 4)*16;
                ldsm4(st + GS_AH + aoff, ah[mt]);
                ldsm4(st + GS_AL + aoff, al[mt]);
            }
            #pragma unroll
            for (int nt = 0; nt < 4; nt++) {
                uint32_t bhj[2] = {bhv[nt][2*ks], bhv[nt][2*ks+1]};
                uint32_t blj[2] = {blv[nt][2*ks], blv[nt][2*ks+1]};
                #pragma unroll
                for (int mt = 0; mt < 2; mt++) {
                    mmabf(acc[mt][nt], ah[mt], bhj);
                    mmabf(acc[mt][nt], ah[mt], blj);
                    mmabf(acc[mt][nt], al[mt], bhj);
                }
            }
        }
        __syncthreads();
    }

    // epilogue
    #pragma unroll
    for (int mt = 0; mt < 2; mt++) {
        #pragma unroll
        for (int nt = 0; nt < 4; nt++) {
            int n  = blockN + warpn*32 + nt*8 + 2*tg;
            float b0 = bias[n], b1 = bias[n+1];
            int m0 = blockM + warpm*32 + mt*16 + gq;
            float v[2][2] = {{acc[mt][nt][0] + b0, acc[mt][nt][1] + b1},
                             {acc[mt][nt][2] + b0, acc[mt][nt][3] + b1}};
            #pragma unroll
            for (int r = 0; r < 2; r++) {
                int m = m0 + r*8;
                if (MODE == 0) {
                    float2 o; o.x = v[r][0]; o.y = v[r][1];
                    *(float2*)(Cout + (size_t)m*DM + n) = o;
                } else {
                    int which = n >> 10, hd = n & 1023;
                    int hh = hd >> 6, d = hd & 63;
                    int bb = m >> 11, l = m & (SEQ-1);
                    int bhid = bb*NH + hh;
                    float v0 = v[r][0], v1 = v[r][1];
                    if (which == 0) { v0 *= 0.125f; v1 *= 0.125f; }
                    __nv_bfloat16 h0, l0, h1, l1;
                    split_hl(v0, h0, l0); split_hl(v1, h1, l1);
                    if (which == 2) {
                        size_t base = ((size_t)bhid*DH + d)*SEQ + l;
                        g_vth[base] = h0; g_vth[base + SEQ] = h1;
                        g_vtl[base] = l0; g_vtl[base + SEQ] = l1;
                    } else {
                        size_t idx = ((size_t)bhid*SEQ + l)*DH + d;
                        __nv_bfloat16* H = which ? g_kh : g_qh;
                        __nv_bfloat16* L = which ? g_kl : g_ql;
                        __nv_bfloat162 hv; hv.x = h0; hv.y = h1;
                        __nv_bfloat162 lv; lv.x = l0; lv.y = l1;
                        *(__nv_bfloat162*)(H + idx) = hv;
                        *(__nv_bfloat162*)(L + idx) = lv;
                    }
                }
            }
        }
    }
}

// ---------------- phase projection --------------------------------------------
__global__ void __launch_bounds__(128) phase_kernel(const float* __restrict__ X,
                                                    const float* __restrict__ PW,
                                                    const float* __restrict__ PB,
                                                    const float* __restrict__ pscale)
{
    __shared__ float xs[DM];
    const int row = blockIdx.x;            // b*L + l
    for (int i = threadIdx.x; i < DM; i += 128) xs[i] = X[(size_t)row*DM + i];
    __syncthreads();
    const int h  = threadIdx.x >> 3;
    const int ln = threadIdx.x & 7;
    float s = 0.f;
    for (int k = ln; k < DM; k += 8) s += xs[k]*PW[(size_t)h*DM + k];
    #pragma unroll
    for (int off = 4; off; off >>= 1) s += __shfl_xor_sync(0xffffffffu, s, off);
    if (ln == 0) {
        float v = tanhf(pscale[0]*(s + PB[h]));
        int b = row >> 11, l = row & (SEQ-1);
        g_pv[((size_t)(b*NH + h))*SEQ + l] = v;
    }
}

// ---------------- fused attention (mma.sync, 2-pass, register P) --------------
// Pass 1 uses single bf16 MMA (hi only) — sum/max tolerance allows it.
#define AT_Q(hl)    (18432u*(unsigned)(hl))
#define AT_K(s,hl)  (36864u  + 18432u*(unsigned)((s)*2+(hl)))
#define AT_V(s,hl)  (110592u + 17408u*(unsigned)((s)*2+(hl)))
#define AT_PK    180224u
#define AT_PK2   188416u
#define AT_PQ    196608u
#define AT_MS    197120u
#define AT_INV   197632u
#define AT_RED   198144u
#define AT_OPART 36864u          /* reuse K buffers post-loop */
#define ATTN_SMEM 200192u

__global__ void __launch_bounds__(512) attn_kernel(float* __restrict__ attn_out,
                                                   const float* __restrict__ rscale_p)
{
    extern __shared__ char smc[];
    const unsigned sb = smem_u32(smc);
    const int t = threadIdx.x, lane = t & 31, w = t >> 5;
    const int R0 = (w >> 1)*16;
    const int chalf = w & 1, C0 = chalf*64;
    const int gq = lane >> 2, tg = lane & 3;
    const int r1 = R0 + gq, r2 = r1 + 8;

    const int qt = blockIdx.x, h = blockIdx.y, b = blockIdx.z;
    const int bh = b*NH + h;
    const float rs = rscale_p[0];

    const __nv_bfloat16* Qh  = g_qh  + ((size_t)bh*SEQ + (size_t)qt*128)*DH;
    const __nv_bfloat16* Ql  = g_ql  + ((size_t)bh*SEQ + (size_t)qt*128)*DH;
    const __nv_bfloat16* Kh  = g_kh  + (size_t)bh*SEQ*DH;
    const __nv_bfloat16* Kl  = g_kl  + (size_t)bh*SEQ*DH;
    const __nv_bfloat16* VTh = g_vth + (size_t)bh*DH*SEQ;
    const __nv_bfloat16* VTl = g_vtl + (size_t)bh*DH*SEQ;
    const float*         PV  = g_pv  + (size_t)bh*SEQ;

    float* pkF  = (float*)(smc + AT_PK);
    float* pk2F = (float*)(smc + AT_PK2);
    float* pqF  = (float*)(smc + AT_PQ);
    float* mS   = (float*)(smc + AT_MS);
    float* invS = (float*)(smc + AT_INV);
    float* redM = (float*)(smc + AT_RED);       // [2][128]
    float* redS = redM + 256;                   // [2][128]

    const int krow = t >> 3, kc8 = (t & 7) << 3;
    const unsigned kso = (unsigned)(krow*72 + kc8)*2;
    const int vdh = t >> 4, vc8 = (t & 15) << 3;
    const unsigned vso = (unsigned)(vdh*136 + vc8)*2;

    auto prefetch_k_hi = [&](int ch, int s) {    // pass-1: hi only
        const __nv_bfloat16* kh = Kh + (size_t)ch*128*DH;
        #pragma unroll
        for (int p = 0; p < 2; p++) {
            int row = krow + p*64;
            cp16(sb + AT_K(s,0) + kso + (unsigned)p*64*144, kh + row*DH + kc8);
        }
    };
    auto prefetch_k = [&](int ch, int s) {
        const __nv_bfloat16* kh = Kh + (size_t)ch*128*DH;
        const __nv_bfloat16* kl = Kl + (size_t)ch*128*DH;
        #pragma unroll
        for (int p = 0; p < 2; p++) {
            int row = krow + p*64;
            unsigned so = kso + (unsigned)p*64*144;
            cp16(sb + AT_K(s,0) + so, kh + row*DH + kc8);
            cp16(sb + AT_K(s,1) + so, kl + row*DH + kc8);
        }
    };
    auto prefetch_v = [&](int ch, int s) {
        #pragma unroll
        for (int p = 0; p < 2; p++) {
            int dh = vdh + p*32;
            unsigned so = vso + (unsigned)p*32*272;
            cp16(sb + AT_V(s,0) + so, VTh + (size_t)dh*SEQ + ch*128 + vc8);
            cp16(sb + AT_V(s,1) + so, VTl + (size_t)dh*SEQ + ch*128 + vc8);
        }
    };

    // stage Q (hi/lo) + phase values
    prefetch_k_hi(0, 0); CP_COMMIT();
    #pragma unroll
    for (int p = 0; p < 2; p++) {
        int i = t + p*512;
        int row = i >> 3, c8 = (i & 7) << 3;
        unsigned so = (unsigned)(row*72 + c8)*2;
        *(uint4*)(smc + AT_Q(0) + so) = *(const uint4*)(Qh + row*DH + c8);
        *(uint4*)(smc + AT_Q(1) + so) = *(const uint4*)(Ql + row*DH + c8);
    }
    for (int i = t; i < SEQ; i += 512) {
        float pv = PV[i];
        pkF[i] = pv; pk2F[i] = -rs*pv*pv;
    }
    if (t < 128) pqF[t] = PV[qt*128 + t];
    __syncthreads();

    // Q fragments (held in registers across both passes)
    uint32_t qh[4][4], ql[4][4];
    #pragma unroll
    for (int ks = 0; ks < 4; ks++) {
        unsigned arow = R0 + (lane & 15);
        unsigned aoff = arow*144 + ks*32 + (lane >> 4)*16;
        ldsm4(sb + AT_Q(0) + aoff, qh[ks]);
        ldsm4(sb + AT_Q(1) + aoff, ql[ks]);
    }

    const float pq1v = pqF[r1], pq2v = pqF[r2];
    const float a1r = 2.f*rs*pq1v, b1r = -rs*pq1v*pq1v;
    const float a2r = 2.f*rs*pq2v, b2r = -rs*pq2v*pq2v;

    // ================= PASS 1: row max + exp-sum (hi-only MMA) ================
    float m1 = -1e30f, s1 = 0.f, m2 = -1e30f, s2 = 0.f;
    for (int ch = 0; ch < NCH; ch++) {
        if (ch + 1 < NCH) { prefetch_k_hi(ch+1, (ch+1)&1); CP_COMMIT(); CP_WAIT(1); }
        else CP_WAIT(0);
        __syncthreads();
        const unsigned kbh = sb + AT_K(ch & 1, 0);

        float acc[8][4] = {};
        #pragma unroll
        for (int nt = 0; nt < 8; nt++) {
            unsigned brow = (unsigned)(C0 + 8*nt + (lane & 7));
            unsigned bbase = brow*144 + (lane >> 3)*16;
            #pragma unroll
            for (int kp = 0; kp < 2; kp++) {
                uint32_t bhv[4];
                ldsm4(kbh + bbase + kp*64, bhv);
                #pragma unroll
                for (int j = 0; j < 2; j++) {
                    int ks = kp*2 + j;
                    uint32_t bhj[2] = {bhv[2*j], bhv[2*j+1]};
                    mmabf(acc[nt], qh[ks], bhj);
                }
            }
        }
        float mc1 = -1e30f, mc2 = -1e30f;
        #pragma unroll
        for (int nt = 0; nt < 8; nt++)
            #pragma unroll
            for (int e = 0; e < 2; e++) {
                int gc = ch*128 + C0 + 8*nt + 2*tg + e;
                float u = pkF[gc], u2 = pk2F[gc];
                mc1 = fmaxf(mc1, acc[nt][e]   + a1r*u + u2);
                mc2 = fmaxf(mc2, acc[nt][2+e] + a2r*u + u2);
            }
        float mn1 = fmaxf(m1, mc1 + b1r), mn2 = fmaxf(m2, mc2 + b2r);
        float ac1 = 0.f, ac2 = 0.f;
        #pragma unroll
        for (int nt = 0; nt < 8; nt++)
            #pragma unroll
            for (int e = 0; e < 2; e++) {
                int gc = ch*128 + C0 + 8*nt + 2*tg + e;
                float u = pkF[gc], u2 = pk2F[gc];
                ac1 += __expf(acc[nt][e]   + a1r*u + u2 + b1r - mn1);
                ac2 += __expf(acc[nt][2+e] + a2r*u + u2 + b2r - mn2);
            }
        s1 = s1*__expf(m1 - mn1) + ac1; m1 = mn1;
        s2 = s2*__expf(m2 - mn2) + ac2; m2 = mn2;
        __syncthreads();
    }
    // reduce across tg lanes, then across column halves
    #pragma unroll
    for (int off = 1; off <= 2; off <<= 1) {
        float mo = __shfl_xor_sync(0xffffffffu, m1, off);
        float so = __shfl_xor_sync(0xffffffffu, s1, off);
        float mm = fmaxf(m1, mo);
        s1 = s1*__expf(m1 - mm) + so*__expf(mo - mm); m1 = mm;
        mo = __shfl_xor_sync(0xffffffffu, m2, off);
        so = __shfl_xor_sync(0xffffffffu, s2, off);
        mm = fmaxf(m2, mo);
        s2 = s2*__expf(m2 - mm) + so*__expf(mo - mm); m2 = mm;
    }
    if (tg == 0) {
        redM[chalf*128 + r1] = m1; redS[chalf*128 + r1] = s1;
        redM[chalf*128 + r2] = m2; redS[chalf*128 + r2] = s2;
    }
    __syncthreads();
    if (t < 128) {
        float ma = redM[t], mb = redM[128 + t];
        float sa = redS[t], sbv = redS[128 + t];
        float mm = fmaxf(ma, mb);
        float ss = sa*__expf(ma - mm) + sbv*__expf(mb - mm);
        mS[t] = mm; invS[t] = 1.f/ss;
    }
    __syncthreads();

    const float i1 = invS[r1], i2 = invS[r2];
    const float c1r = b1r - mS[r1], c2r = b2r - mS[r2];   // fold -m into row const

    // ================= PASS 2: attn weights + P@V (register P) ================
    float o[8][4] = {};
    prefetch_k(0, 0); prefetch_v(0, 0); CP_COMMIT();
    for (int ch = 0; ch < NCH; ch++) {
        if (ch + 1 < NCH) {
            prefetch_k(ch+1, (ch+1)&1); prefetch_v(ch+1, (ch+1)&1);
            CP_COMMIT(); CP_WAIT(1);
        } else CP_WAIT(0);
        __syncthreads();
        const unsigned kbh = sb + AT_K(ch & 1, 0), kbl = sb + AT_K(ch & 1, 1);
        const unsigned vbh = sb + AT_V(ch & 1, 0), vbl = sb + AT_V(ch & 1, 1);

        #pragma unroll
        for (int half = 0; half < 2; half++) {
            // --- QK scores for nt in [4*half, 4*half+4) ---
            float acc[4][4] = {};
            #pragma unroll
            for (int nt4 = 0; nt4 < 4; nt4++) {
                int nt = 4*half + nt4;
                unsigned brow = (unsigned)(C0 + 8*nt + (lane & 7));
                unsigned bbase = brow*144 + (lane >> 3)*16;
                #pragma unroll
                for (int kp = 0; kp < 2; kp++) {
                    uint32_t bhv[4], blv[4];
                    ldsm4(kbh + bbase + kp*64, bhv);
                    ldsm4(kbl + bbase + kp*64, blv);
                    #pragma unroll
                    for (int j = 0; j < 2; j++) {
                        int ks = kp*2 + j;
                        uint32_t bhj[2] = {bhv[2*j], bhv[2*j+1]};
                        uint32_t blj[2] = {blv[2*j], blv[2*j+1]};
                        mmabf(acc[nt4], qh[ks], bhj);
                        mmabf(acc[nt4], qh[ks], blj);
                        mmabf(acc[nt4], ql[ks], bhj);
                    }
                }
            }
            // --- exp -> attn write + P A-fragments in registers ---
            uint32_t pAh[2][4], pAl[2][4];      // [local kstep][a-reg]
            #pragma unroll
            for (int nt4 = 0; nt4 < 4; nt4++) {
                int nt = 4*half + nt4;
                int c0 = C0 + 8*nt + 2*tg;
                int gc = ch*128 + c0;
                float u0 = pkF[gc], u20 = pk2F[gc];
                float u1 = pkF[gc+1], u21 = pk2F[gc+1];
                float p10 = __expf(acc[nt4][0] + a1r*u0 + u20 + c1r)*i1;
                float p11 = __expf(acc[nt4][1] + a1r*u1 + u21 + c1r)*i1;
                float p20 = __expf(acc[nt4][2] + a2r*u0 + u20 + c2r)*i2;
                float p21 = __expf(acc[nt4][3] + a2r*u1 + u21 + c2r)*i2;
                float2 w1; w1.x = p10; w1.y = p11;
                float2 w2; w2.x = p20; w2.y = p21;
                *(float2*)(attn_out + ((size_t)bh*SEQ + (size_t)qt*128 + r1)*SEQ + gc) = w1;
                *(float2*)(attn_out + ((size_t)bh*SEQ + (size_t)qt*128 + r2)*SEQ + gc) = w2;
                int kl_ = nt4 >> 1, pos = (nt4 & 1)*2;
                pAh[kl_][pos+0] = pack_hl_hi(p10, p11);
                pAh[kl_][pos+1] = pack_hl_hi(p20, p21);
                pAl[kl_][pos+0] = pack_hl_lo(p10, p11);
                pAl[kl_][pos+1] = pack_hl_lo(p20, p21);
            }
            // --- P @ V for this 32-key group ---
            #pragma unroll
            for (int nt = 0; nt < 8; nt++) {
                unsigned brow = (unsigned)(8*nt + (lane & 7));
                unsigned boff = brow*272 + (unsigned)C0*2 + (unsigned)half*64 + (lane >> 3)*16;
                uint32_t bvh[4], bvl[4];
                ldsm4(vbh + boff, bvh);
                ldsm4(vbl + boff, bvl);
                #pragma unroll
                for (int j = 0; j < 2; j++) {
                    uint32_t bhj[2] = {bvh[2*j], bvh[2*j+1]};
                    uint32_t blj[2] = {bvl[2*j], bvl[2*j+1]};
                    mmabf(o[nt], pAh[j], bhj);
                    mmabf(o[nt], pAh[j], blj);
                    mmabf(o[nt], pAl[j], bhj);
                }
            }
        }
        __syncthreads();
    }

    // ---- merge column halves and write ctx bf16 hi/lo ----
    float* part = (float*)(smc + AT_OPART);     // [128][64]
    if (chalf == 1) {
        #pragma unroll
        for (int nt = 0; nt < 8; nt++) {
            float2 a; a.x = o[nt][0]; a.y = o[nt][1];
            float2 c; c.x = o[nt][2]; c.y = o[nt][3];
            *(float2*)&part[r1*64 + 8*nt + 2*tg] = a;
            *(float2*)&part[r2*64 + 8*nt + 2*tg] = c;
        }
    }
    __syncthreads();
    if (chalf == 0) {
        #pragma unroll
        for (int nt = 0; nt < 8; nt++) {
            int c = 8*nt + 2*tg;
            float2 q1 = *(const float2*)&part[r1*64 + c];
            float2 q2 = *(const float2*)&part[r2*64 + c];
            float v10 = o[nt][0] + q1.x, v11 = o[nt][1] + q1.y;
            float v20 = o[nt][2] + q2.x, v21 = o[nt][3] + q2.y;
            __nv_bfloat16 h0, l0, h1_, l1_;
            size_t idx1 = ((size_t)b*SEQ + (size_t)qt*128 + r1)*DM + h*DH + c;
            size_t idx2 = ((size_t)b*SEQ + (size_t)qt*128 + r2)*DM + h*DH + c;
            __nv_bfloat162 hv, lv;
            split_hl(v10, h0, l0); split_hl(v11, h1_, l1_);
            hv.x = h0; hv.y = h1_; lv.x = l0; lv.y = l1_;
            *(__nv_bfloat162*)(g_ctxh + idx1) = hv;
            *(__nv_bfloat162*)(g_ctxl + idx1) = lv;
            split_hl(v20, h0, l0); split_hl(v21, h1_, l1_);
            hv.x = h0; hv.y = h1_; lv.x = l0; lv.y = l1_;
            *(__nv_bfloat162*)(g_ctxh + idx2) = hv;
            *(__nv_bfloat162*)(g_ctxl + idx2) = lv;
        }
    }
}

// ---------------- launch ------------------------------------------------------
extern "C" void kernel_launch(void* const* d_in, const int* in_sizes, int n_in,
                              void* d_out, int out_size)
{
    const float* x       = (const float*)d_in[0];
    const float* qkv_w   = (const float*)d_in[1];
    const float* qkv_b   = (const float*)d_in[2];
    const float* out_w   = (const float*)d_in[3];
    const float* out_b   = (const float*)d_in[4];
    const float* phase_w = (const float*)d_in[5];
    const float* phase_b = (const float*)d_in[6];
    const float* rscale  = (const float*)d_in[7];
    const float* pscale  = (const float*)d_in[8];

    float* out  = (float*)d_out;                       // [B,L,D]
    float* attn = out + (size_t)NB*SEQ*DM;             // [B,H,L,L]

    __nv_bfloat16 *d_xh, *d_xl, *d_wqh, *d_wql, *d_woh, *d_wol, *d_ctxh, *d_ctxl;
    cudaGetSymbolAddress((void**)&d_xh,  g_xh);
    cudaGetSymbolAddress((void**)&d_xl,  g_xl);
    cudaGetSymbolAddress((void**)&d_wqh, g_wqh);
    cudaGetSymbolAddress((void**)&d_wql, g_wql);
    cudaGetSymbolAddress((void**)&d_woh, g_woh);
    cudaGetSymbolAddress((void**)&d_wol, g_wol);
    cudaGetSymbolAddress((void**)&d_ctxh, g_ctxh);
    cudaGetSymbolAddress((void**)&d_ctxl, g_ctxl);

    cudaFuncSetAttribute(gemm_kernel<0>, cudaFuncAttributeMaxDynamicSharedMemorySize, GEMM_SMEM);
    cudaFuncSetAttribute(gemm_kernel<1>, cudaFuncAttributeMaxDynamicSharedMemorySize, GEMM_SMEM);
    cudaFuncSetAttribute(attn_kernel, cudaFuncAttributeMaxDynamicSharedMemorySize, ATTN_SMEM);

    cvt_kernel<<<512, 256>>>(x,     d_xh,  d_xl,  MTOT*DM);
    cvt_kernel<<<512, 256>>>(qkv_w, d_wqh, d_wql, 3*DM*DM);
    cvt_kernel<<<512, 256>>>(out_w, d_woh, d_wol, DM*DM);

    gemm_kernel<1><<<dim3(3*DM/64, MTOT/128), 256, GEMM_SMEM>>>(
        d_xh, d_xl, d_wqh, d_wql, qkv_b, nullptr);
    phase_kernel<<<dim3(NB*SEQ), 128>>>(x, phase_w, phase_b, pscale);
    attn_kernel<<<dim3(SEQ/128, NH, NB), 512, ATTN_SMEM>>>(attn, rscale);

    gemm_kernel<0><<<dim3(DM/64, MTOT/128), 256, GEMM_SMEM>>>(
        d_ctxh, d_ctxl, d_woh, d_wol, out_b, out);
}